// round 4
// baseline (speedup 1.0000x reference)
#include <cuda_runtime.h>
#include <cstdint>

#define EDIM    8
#define NCODES  1024
#define NPAIR   512          // NCODES/2
#define GSIZE   8            // pairs per tournament group
#define NGROUP  (NPAIR/GSIZE)
#define SP      32768        // 32*32*32 spatial per batch
#define THREADS 128
#define QPT     2            // queries per thread

typedef unsigned long long ull;

// ---- device scratch (no allocations; self-resetting across graph replays) ----
__device__ float    g_partial[4096];   // per-block loss partials (overwritten each run)
__device__ int      g_used[NCODES];    // set by main, counted+reset by finalizer
__device__ unsigned g_ticket = 0;      // completion ticket; finalizer resets to 0

// ---- packed f32x2 helpers (Blackwell FFMA2 path, PTX-only) ----
__device__ __forceinline__ ull pack2(float lo, float hi){
    ull d;
    asm("mov.b64 %0, {%1, %2};" : "=l"(d)
        : "r"(__float_as_uint(lo)), "r"(__float_as_uint(hi)));
    return d;
}
__device__ __forceinline__ ull fma2(ull a, ull b, ull c){
    ull d; asm("fma.rn.f32x2 %0, %1, %2, %3;" : "=l"(d) : "l"(a), "l"(b), "l"(c));
    return d;
}
__device__ __forceinline__ ull mul2(ull a, ull b){
    ull d; asm("mul.rn.f32x2 %0, %1, %2;" : "=l"(d) : "l"(a), "l"(b));
    return d;
}
__device__ __forceinline__ ull add2(ull a, ull b){
    ull d; asm("add.rn.f32x2 %0, %1, %2;" : "=l"(d) : "l"(a), "l"(b));
    return d;
}
union U64F2 { ull u; float2 f; };
__device__ __forceinline__ float2 asf2(ull v){ U64F2 x; x.u = v; return x.f; }

// Bit-exact pair distance: d_pair = fma2(dot2, {-2,-2}, add2(ee2, zz2))
// (this exact op structure reproduces the reference's rounding; do not change)
__device__ __forceinline__ ull pair_dist(const ulonglong2* ep, ull eep,
                                         const ull* zp, ull zzp, ull m2){
    const ulonglong2 e01 = ep[0];
    const ulonglong2 e23 = ep[1];
    const ulonglong2 e45 = ep[2];
    const ulonglong2 e67 = ep[3];
    ull a = mul2(zp[0], e01.x);
    a = fma2(zp[1], e01.y, a);
    a = fma2(zp[2], e23.x, a);
    a = fma2(zp[3], e23.y, a);
    a = fma2(zp[4], e45.x, a);
    a = fma2(zp[5], e45.y, a);
    a = fma2(zp[6], e67.x, a);
    a = fma2(zp[7], e67.y, a);
    return fma2(a, m2, add2(eep, zzp));
}

// ---- single fused kernel: tournament search + epilogue + ticket finalize ----
__global__ __launch_bounds__(THREADS, 6) void vq_main(
    const float* __restrict__ z,
    const float* __restrict__ emb,
    float* __restrict__ out,
    int Nvec, int nblocks)
{
    __shared__ __align__(16) float2 sE[NPAIR * EDIM];  // pair-packed codebook, 32KB
    __shared__ __align__(16) float  sEE[NCODES];       // ||e||^2, 4KB
    __shared__ float sRed[THREADS / 32];
    __shared__ bool  sLast;

    // Stage codebook: sE[p*8+c] = (e[2p][c], e[2p+1][c])
    for (int i = threadIdx.x; i < NPAIR * EDIM; i += THREADS){
        int p = i >> 3, c = i & 7;
        sE[i] = make_float2(emb[(2*p)*EDIM + c], emb[(2*p+1)*EDIM + c]);
    }
    for (int j = threadIdx.x; j < NCODES; j += THREADS){
        float s = 0.f;
        #pragma unroll
        for (int c = 0; c < EDIM; c++){ float e = emb[j*EDIM + c]; s = fmaf(e, e, s); }
        sEE[j] = s;
    }
    __syncthreads();

    const int part = Nvec >> 1;                 // Nvec / QPT
    const int t = blockIdx.x * THREADS + threadIdx.x;
    float lossLocal = 0.f;

    if (t < part) {
        int nq[QPT], bq[QPT], sq[QPT];
        ull zp[QPT][EDIM];
        ull zzp[QPT];

        #pragma unroll
        for (int q = 0; q < QPT; q++){
            nq[q] = t + q * part;
            bq[q] = nq[q] >> 15;
            sq[q] = nq[q] & (SP - 1);
            const float* zptr = z + (size_t)bq[q] * (EDIM * SP) + sq[q];
            float zz = 0.f;
            #pragma unroll
            for (int c = 0; c < EDIM; c++){
                float v = zptr[c * SP];
                zp[q][c] = pack2(v, v);
                zz = fmaf(v, v, zz);
            }
            zzp[q] = pack2(zz, zz);
        }
        const ull m2 = pack2(-2.f, -2.f);

        float best[QPT];
        int   bg[QPT];                          // winning GROUP index
        #pragma unroll
        for (int q = 0; q < QPT; q++){ best[q] = 3.4e38f; bg[q] = 0; }

        for (int g = 0; g < NGROUP; g++){
            float gdm[QPT];
            #pragma unroll
            for (int q = 0; q < QPT; q++) gdm[q] = 3.4e38f;

            #pragma unroll
            for (int j = 0; j < GSIZE; j++){
                const int p = g * GSIZE + j;
                const ulonglong2* ep = reinterpret_cast<const ulonglong2*>(sE + p * EDIM);
                const ull eep = *reinterpret_cast<const ull*>(sEE + 2 * p);
                #pragma unroll
                for (int q = 0; q < QPT; q++){
                    float2 df = asf2(pair_dist(ep, eep, zp[q], zzp[q], m2));
                    gdm[q] = fminf(gdm[q], fminf(df.x, df.y));
                }
            }
            #pragma unroll
            for (int q = 0; q < QPT; q++){
                bool upd = gdm[q] < best[q];    // strict: first group with min wins
                bg[q]   = upd ? g : bg[q];
                best[q] = fminf(best[q], gdm[q]);
            }
        }

        // Epilogue: rescan winning group (bit-exact), first-occurrence argmin
        const int n_z = Nvec * EDIM;
        #pragma unroll
        for (int q = 0; q < QPT; q++){
            float bq_d = 3.4e38f;
            int bi = 0, bp = 0, bsel = 0;
            #pragma unroll
            for (int j = 0; j < GSIZE; j++){
                const int p = bg[q] * GSIZE + j;
                const ulonglong2* ep = reinterpret_cast<const ulonglong2*>(sE + p * EDIM);
                const ull eep = *reinterpret_cast<const ull*>(sEE + 2 * p);
                float2 df = asf2(pair_dist(ep, eep, zp[q], zzp[q], m2));
                if (df.x < bq_d){ bq_d = df.x; bi = 2*p;     bp = p; bsel = 0; }
                if (df.y < bq_d){ bq_d = df.y; bi = 2*p + 1; bp = p; bsel = 1; }
            }

            float* o = out + (size_t)bq[q] * (EDIM * SP) + sq[q];
            #pragma unroll
            for (int c = 0; c < EDIM; c++){
                float2 ev = sE[bp * EDIM + c];
                float e = bsel ? ev.y : ev.x;
                o[c * SP] = e;
                float zc = asf2(zp[q][c]).x;
                float dfc = e - zc;
                lossLocal = fmaf(dfc, dfc, lossLocal);
            }
            out[n_z + 2 + nq[q]] = (float)bi;
            g_used[bi] = 1;
        }
    }

    // Block-reduce loss -> deterministic per-block partial
    #pragma unroll
    for (int o = 16; o > 0; o >>= 1)
        lossLocal += __shfl_down_sync(0xffffffff, lossLocal, o);
    const int lane = threadIdx.x & 31, w = threadIdx.x >> 5;
    if (lane == 0) sRed[w] = lossLocal;
    __syncthreads();
    if (threadIdx.x == 0){
        float v = 0.f;
        #pragma unroll
        for (int i = 0; i < THREADS / 32; i++) v += sRed[i];
        g_partial[blockIdx.x] = v;
        __threadfence();
        unsigned old = atomicAdd(&g_ticket, 1u);
        sLast = (old == (unsigned)(nblocks - 1));
    }
    __syncthreads();

    // Last block to finish performs finalization (deterministic result)
    if (sLast){
        __threadfence();
        const int n_z = Nvec * EDIM;

        int cnt = 0;
        for (int i = threadIdx.x; i < NCODES; i += THREADS){
            cnt += (g_used[i] != 0);
            g_used[i] = 0;                      // reset for next replay
        }
        float s = 0.f;
        for (int i = threadIdx.x; i < nblocks; i += THREADS) s += g_partial[i];

        #pragma unroll
        for (int o = 16; o > 0; o >>= 1){
            s   += __shfl_down_sync(0xffffffff, s, o);
            cnt += __shfl_down_sync(0xffffffff, cnt, o);
        }
        __shared__ float rs[THREADS / 32];
        __shared__ int   rc[THREADS / 32];
        if (lane == 0){ rs[w] = s; rc[w] = cnt; }
        __syncthreads();
        if (threadIdx.x == 0){
            float total = 0.f; int ctotal = 0;
            #pragma unroll
            for (int i = 0; i < THREADS / 32; i++){ total += rs[i]; ctotal += rc[i]; }
            // loss = beta*mean + mean = 1.25 * sum((z_q - z)^2) / n_z
            out[n_z]     = 1.25f * total / (float)n_z;
            out[n_z + 1] = (float)ctotal;
            __threadfence();
            g_ticket = 0;                       // reset for next graph replay
        }
    }
}

extern "C" void kernel_launch(void* const* d_in, const int* in_sizes, int n_in,
                              void* d_out, int out_size)
{
    const float* z   = (const float*)d_in[0];
    const float* emb = (const float*)d_in[1];
    float* out = (float*)d_out;

    const int n_z  = in_sizes[0];      // 2,097,152
    const int Nvec = n_z / EDIM;       // 262,144

    const int part = Nvec / QPT;
    const int nblocks = (part + THREADS - 1) / THREADS;   // 1024
    vq_main<<<nblocks, THREADS>>>(z, emb, out, Nvec, nblocks);
}

// round 5
// speedup vs baseline: 1.0274x; 1.0274x over previous
#include <cuda_runtime.h>
#include <cstdint>

#define EDIM    8
#define NCODES  1024
#define NPAIR   512          // NCODES/2
#define SP      32768        // 32*32*32 spatial per batch
#define THREADS 64
#define QPT     4            // queries per thread

typedef unsigned long long ull;

// ---- device scratch (no allocations; self-resetting across graph replays) ----
__device__ float    g_partial[4096];   // per-block loss partials (overwritten each run)
__device__ int      g_used[NCODES];    // set by main, counted+reset by finalizer
__device__ unsigned g_ticket = 0;      // completion ticket; finalizer resets to 0

// ---- packed f32x2 helpers (Blackwell FFMA2 path, PTX-only) ----
__device__ __forceinline__ ull pack2(float lo, float hi){
    ull d;
    asm("mov.b64 %0, {%1, %2};" : "=l"(d)
        : "r"(__float_as_uint(lo)), "r"(__float_as_uint(hi)));
    return d;
}
__device__ __forceinline__ ull fma2(ull a, ull b, ull c){
    ull d; asm("fma.rn.f32x2 %0, %1, %2, %3;" : "=l"(d) : "l"(a), "l"(b), "l"(c));
    return d;
}
__device__ __forceinline__ ull mul2(ull a, ull b){
    ull d; asm("mul.rn.f32x2 %0, %1, %2;" : "=l"(d) : "l"(a), "l"(b));
    return d;
}
__device__ __forceinline__ ull add2(ull a, ull b){
    ull d; asm("add.rn.f32x2 %0, %1, %2;" : "=l"(d) : "l"(a), "l"(b));
    return d;
}
union U64F2 { ull u; float2 f; };
__device__ __forceinline__ float2 asf2(ull v){ U64F2 x; x.u = v; return x.f; }

// Bit-exact pair distance: d_pair = fma2(dot2, {-2,-2}, add2(ee2, zz2))
// (this exact op structure reproduces the reference's rounding; do not change)
__device__ __forceinline__ ull pair_dist(const ulonglong2* ep, ull eep,
                                         const ull* zp, ull zzp, ull m2){
    const ulonglong2 e01 = ep[0];
    const ulonglong2 e23 = ep[1];
    const ulonglong2 e45 = ep[2];
    const ulonglong2 e67 = ep[3];
    ull a = mul2(zp[0], e01.x);
    a = fma2(zp[1], e01.y, a);
    a = fma2(zp[2], e23.x, a);
    a = fma2(zp[3], e23.y, a);
    a = fma2(zp[4], e45.x, a);
    a = fma2(zp[5], e45.y, a);
    a = fma2(zp[6], e67.x, a);
    a = fma2(zp[7], e67.y, a);
    return fma2(a, m2, add2(eep, zzp));
}

// ---- single fused kernel: search + epilogue + ticket-gated finalize ----
__global__ __launch_bounds__(THREADS, 6) void vq_main(
    const float* __restrict__ z,
    const float* __restrict__ emb,
    float* __restrict__ out,
    int Nvec, int nblocks)
{
    __shared__ __align__(16) float2 sE[NPAIR * EDIM];  // pair-packed codebook, 32KB
    __shared__ __align__(16) float  sEE[NCODES];       // ||e||^2, 4KB
    __shared__ float sRed[THREADS / 32];
    __shared__ bool  sLast;

    // Stage codebook: sE[p*8+c] = (e[2p][c], e[2p+1][c])
    for (int i = threadIdx.x; i < NPAIR * EDIM; i += THREADS){
        int p = i >> 3, c = i & 7;
        sE[i] = make_float2(emb[(2*p)*EDIM + c], emb[(2*p+1)*EDIM + c]);
    }
    for (int j = threadIdx.x; j < NCODES; j += THREADS){
        float s = 0.f;
        #pragma unroll
        for (int c = 0; c < EDIM; c++){ float e = emb[j*EDIM + c]; s = fmaf(e, e, s); }
        sEE[j] = s;
    }
    __syncthreads();

    const int part = Nvec >> 2;                 // Nvec / QPT
    const int t = blockIdx.x * THREADS + threadIdx.x;
    float lossLocal = 0.f;

    if (t < part) {
        int nq[QPT], bq[QPT], sq[QPT];
        ull zp[QPT][EDIM];
        ull zzp[QPT];

        #pragma unroll
        for (int q = 0; q < QPT; q++){
            nq[q] = t + q * part;
            bq[q] = nq[q] >> 15;
            sq[q] = nq[q] & (SP - 1);
            const float* zptr = z + (size_t)bq[q] * (EDIM * SP) + sq[q];
            float zz = 0.f;
            #pragma unroll
            for (int c = 0; c < EDIM; c++){
                float v = zptr[c * SP];
                zp[q][c] = pack2(v, v);
                zz = fmaf(v, v, zz);
            }
            zzp[q] = pack2(zz, zz);
        }
        const ull m2 = pack2(-2.f, -2.f);

        float best[QPT];
        int   bip[QPT];                         // winning PAIR index
        #pragma unroll
        for (int q = 0; q < QPT; q++){ best[q] = 3.4e38f; bip[q] = 0; }

        #pragma unroll 4
        for (int p = 0; p < NPAIR; p++){
            const ulonglong2* ep = reinterpret_cast<const ulonglong2*>(sE + p * EDIM);
            const ull eep = *reinterpret_cast<const ull*>(sEE + 2 * p);
            #pragma unroll
            for (int q = 0; q < QPT; q++){
                float2 df = asf2(pair_dist(ep, eep, zp[q], zzp[q], m2));
                float dm = fminf(df.x, df.y);
                bool upd = dm < best[q];        // strict: first pair with min wins
                bip[q] = upd ? p : bip[q];
                best[q] = fminf(best[q], dm);
            }
        }

        // Epilogue: resolve even/odd half (bit-exact recompute), gather, loss, idx
        const int n_z = Nvec * EDIM;
        #pragma unroll
        for (int q = 0; q < QPT; q++){
            const int p = bip[q];
            const ulonglong2* ep = reinterpret_cast<const ulonglong2*>(sE + p * EDIM);
            const ull eep = *reinterpret_cast<const ull*>(sEE + 2 * p);
            float2 df = asf2(pair_dist(ep, eep, zp[q], zzp[q], m2));
            const int sel = (df.y < df.x) ? 1 : 0;   // tie -> even (first index)
            const int bi = 2 * p + sel;

            float* o = out + (size_t)bq[q] * (EDIM * SP) + sq[q];
            #pragma unroll
            for (int c = 0; c < EDIM; c++){
                float2 ev = sE[p * EDIM + c];
                float e = sel ? ev.y : ev.x;
                o[c * SP] = e;
                float zc = asf2(zp[q][c]).x;
                float dfc = e - zc;
                lossLocal = fmaf(dfc, dfc, lossLocal);
            }
            out[n_z + 2 + nq[q]] = (float)bi;
            g_used[bi] = 1;
        }
    }

    // Block-reduce loss -> deterministic per-block partial
    #pragma unroll
    for (int o = 16; o > 0; o >>= 1)
        lossLocal += __shfl_down_sync(0xffffffff, lossLocal, o);
    const int lane = threadIdx.x & 31, w = threadIdx.x >> 5;
    if (lane == 0) sRed[w] = lossLocal;
    __syncthreads();
    if (threadIdx.x == 0){
        float v = 0.f;
        #pragma unroll
        for (int i = 0; i < THREADS / 32; i++) v += sRed[i];
        g_partial[blockIdx.x] = v;
        __threadfence();
        unsigned old = atomicAdd(&g_ticket, 1u);
        sLast = (old == (unsigned)(nblocks - 1));
    }
    __syncthreads();

    // Last block to finish performs finalization (deterministic result)
    if (sLast){
        __threadfence();
        const int n_z = Nvec * EDIM;

        int cnt = 0;
        for (int i = threadIdx.x; i < NCODES; i += THREADS){
            cnt += (g_used[i] != 0);
            g_used[i] = 0;                      // reset for next replay
        }
        float s = 0.f;
        for (int i = threadIdx.x; i < nblocks; i += THREADS) s += g_partial[i];

        #pragma unroll
        for (int o = 16; o > 0; o >>= 1){
            s   += __shfl_down_sync(0xffffffff, s, o);
            cnt += __shfl_down_sync(0xffffffff, cnt, o);
        }
        __shared__ float rs[THREADS / 32];
        __shared__ int   rc[THREADS / 32];
        if (lane == 0){ rs[w] = s; rc[w] = cnt; }
        __syncthreads();
        if (threadIdx.x == 0){
            float total = 0.f; int ctotal = 0;
            #pragma unroll
            for (int i = 0; i < THREADS / 32; i++){ total += rs[i]; ctotal += rc[i]; }
            // loss = beta*mean + mean = 1.25 * sum((z_q - z)^2) / n_z
            out[n_z]     = 1.25f * total / (float)n_z;
            out[n_z + 1] = (float)ctotal;
            __threadfence();
            g_ticket = 0;                       // reset for next graph replay
        }
    }
}

extern "C" void kernel_launch(void* const* d_in, const int* in_sizes, int n_in,
                              void* d_out, int out_size)
{
    const float* z   = (const float*)d_in[0];
    const float* emb = (const float*)d_in[1];
    float* out = (float*)d_out;

    const int n_z  = in_sizes[0];      // 2,097,152
    const int Nvec = n_z / EDIM;       // 262,144

    const int part = Nvec / QPT;
    const int nblocks = (part + THREADS - 1) / THREADS;   // 1024
    vq_main<<<nblocks, THREADS>>>(z, emb, out, Nvec, nblocks);
}

// round 6
// speedup vs baseline: 1.1380x; 1.1076x over previous
#include <cuda_runtime.h>
#include <cstdint>

#define EDIM    8
#define NCODES  1024
#define NPAIR   512          // NCODES/2
#define SP      32768        // 32*32*32 spatial per batch
#define THREADS 128
#define QPT     2            // queries per thread

typedef unsigned long long ull;

// ---- device scratch (no allocations; self-resetting across graph replays) ----
__device__ float    g_partial[4096];   // per-block loss partials (overwritten each run)
__device__ int      g_used[NCODES];    // set by main, counted+reset by finalizer
__device__ unsigned g_ticket = 0;      // completion ticket; finalizer resets to 0

// ---- packed f32x2 helpers (Blackwell FFMA2 path, PTX-only) ----
__device__ __forceinline__ ull pack2(float lo, float hi){
    ull d;
    asm("mov.b64 %0, {%1, %2};" : "=l"(d)
        : "r"(__float_as_uint(lo)), "r"(__float_as_uint(hi)));
    return d;
}
__device__ __forceinline__ ull fma2(ull a, ull b, ull c){
    ull d; asm("fma.rn.f32x2 %0, %1, %2, %3;" : "=l"(d) : "l"(a), "l"(b), "l"(c));
    return d;
}
__device__ __forceinline__ ull mul2(ull a, ull b){
    ull d; asm("mul.rn.f32x2 %0, %1, %2;" : "=l"(d) : "l"(a), "l"(b));
    return d;
}
__device__ __forceinline__ ull add2(ull a, ull b){
    ull d; asm("add.rn.f32x2 %0, %1, %2;" : "=l"(d) : "l"(a), "l"(b));
    return d;
}
union U64F2 { ull u; float2 f; };
__device__ __forceinline__ float2 asf2(ull v){ U64F2 x; x.u = v; return x.f; }

// Bit-exact pair distance: d_pair = fma2(dot2, {-2,-2}, add2(ee2, zz2))
// (this exact op structure reproduces the reference's rounding; do not change)
__device__ __forceinline__ ull pair_dist(const ulonglong2* ep, ull eep,
                                         const ull* zp, ull zzp, ull m2){
    const ulonglong2 e01 = ep[0];
    const ulonglong2 e23 = ep[1];
    const ulonglong2 e45 = ep[2];
    const ulonglong2 e67 = ep[3];
    ull a = mul2(zp[0], e01.x);
    a = fma2(zp[1], e01.y, a);
    a = fma2(zp[2], e23.x, a);
    a = fma2(zp[3], e23.y, a);
    a = fma2(zp[4], e45.x, a);
    a = fma2(zp[5], e45.y, a);
    a = fma2(zp[6], e67.x, a);
    a = fma2(zp[7], e67.y, a);
    return fma2(a, m2, add2(eep, zzp));
}

// ---- single fused kernel: search + epilogue + ticket-gated finalize ----
__global__ __launch_bounds__(THREADS, 5) void vq_main(
    const float* __restrict__ z,
    const float* __restrict__ emb,
    float* __restrict__ out,
    int Nvec, int nblocks)
{
    __shared__ __align__(16) float2 sE[NPAIR * EDIM];  // pair-packed codebook, 32KB
    __shared__ __align__(16) float  sEE[NCODES];       // ||e||^2, 4KB
    __shared__ float sRed[THREADS / 32];
    __shared__ bool  sLast;

    // Stage codebook: sE[p*8+c] = (e[2p][c], e[2p+1][c])
    for (int i = threadIdx.x; i < NPAIR * EDIM; i += THREADS){
        int p = i >> 3, c = i & 7;
        sE[i] = make_float2(emb[(2*p)*EDIM + c], emb[(2*p+1)*EDIM + c]);
    }
    for (int j = threadIdx.x; j < NCODES; j += THREADS){
        float s = 0.f;
        #pragma unroll
        for (int c = 0; c < EDIM; c++){ float e = emb[j*EDIM + c]; s = fmaf(e, e, s); }
        sEE[j] = s;
    }
    __syncthreads();

    const int part = Nvec >> 1;                 // Nvec / QPT
    const int t = blockIdx.x * THREADS + threadIdx.x;
    float lossLocal = 0.f;

    if (t < part) {
        int nq[QPT], bq[QPT], sq[QPT];
        ull zp[QPT][EDIM];
        ull zzp[QPT];

        #pragma unroll
        for (int q = 0; q < QPT; q++){
            nq[q] = t + q * part;
            bq[q] = nq[q] >> 15;
            sq[q] = nq[q] & (SP - 1);
            const float* zptr = z + (size_t)bq[q] * (EDIM * SP) + sq[q];
            float zz = 0.f;
            #pragma unroll
            for (int c = 0; c < EDIM; c++){
                float v = zptr[c * SP];
                zp[q][c] = pack2(v, v);
                zz = fmaf(v, v, zz);
            }
            zzp[q] = pack2(zz, zz);
        }
        const ull m2 = pack2(-2.f, -2.f);

        float best[QPT];
        int   bip[QPT];                         // winning PAIR index
        #pragma unroll
        for (int q = 0; q < QPT; q++){ best[q] = 3.4e38f; bip[q] = 0; }

        // Two pairs per iteration with structurally independent distance chains
        // (4 chains in flight: 2 pairs x 2 queries), unrolled 2x -> 4 pairs/iter.
        #pragma unroll 2
        for (int p = 0; p < NPAIR; p += 2){
            const ulonglong2* epA = reinterpret_cast<const ulonglong2*>(sE + p * EDIM);
            const ulonglong2* epB = reinterpret_cast<const ulonglong2*>(sE + (p + 1) * EDIM);
            const ull eepA = *reinterpret_cast<const ull*>(sEE + 2 * p);
            const ull eepB = *reinterpret_cast<const ull*>(sEE + 2 * p + 2);

            float2 dA0 = asf2(pair_dist(epA, eepA, zp[0], zzp[0], m2));
            float2 dB0 = asf2(pair_dist(epB, eepB, zp[0], zzp[0], m2));
            float2 dA1 = asf2(pair_dist(epA, eepA, zp[1], zzp[1], m2));
            float2 dB1 = asf2(pair_dist(epB, eepB, zp[1], zzp[1], m2));

            // sequential compares preserve first-occurrence argmin
            {
                float dm = fminf(dA0.x, dA0.y);
                bool u = dm < best[0]; bip[0] = u ? p : bip[0]; best[0] = fminf(best[0], dm);
                dm = fminf(dB0.x, dB0.y);
                u = dm < best[0]; bip[0] = u ? (p + 1) : bip[0]; best[0] = fminf(best[0], dm);
            }
            {
                float dm = fminf(dA1.x, dA1.y);
                bool u = dm < best[1]; bip[1] = u ? p : bip[1]; best[1] = fminf(best[1], dm);
                dm = fminf(dB1.x, dB1.y);
                u = dm < best[1]; bip[1] = u ? (p + 1) : bip[1]; best[1] = fminf(best[1], dm);
            }
        }

        // Epilogue: resolve even/odd half (bit-exact recompute), gather, loss, idx
        const int n_z = Nvec * EDIM;
        #pragma unroll
        for (int q = 0; q < QPT; q++){
            const int p = bip[q];
            const ulonglong2* ep = reinterpret_cast<const ulonglong2*>(sE + p * EDIM);
            const ull eep = *reinterpret_cast<const ull*>(sEE + 2 * p);
            float2 df = asf2(pair_dist(ep, eep, zp[q], zzp[q], m2));
            const int sel = (df.y < df.x) ? 1 : 0;   // tie -> even (first index)
            const int bi = 2 * p + sel;

            float* o = out + (size_t)bq[q] * (EDIM * SP) + sq[q];
            #pragma unroll
            for (int c = 0; c < EDIM; c++){
                float2 ev = sE[p * EDIM + c];
                float e = sel ? ev.y : ev.x;
                o[c * SP] = e;
                float zc = asf2(zp[q][c]).x;
                float dfc = e - zc;
                lossLocal = fmaf(dfc, dfc, lossLocal);
            }
            out[n_z + 2 + nq[q]] = (float)bi;
            g_used[bi] = 1;
        }
    }

    // Block-reduce loss -> deterministic per-block partial
    #pragma unroll
    for (int o = 16; o > 0; o >>= 1)
        lossLocal += __shfl_down_sync(0xffffffff, lossLocal, o);
    const int lane = threadIdx.x & 31, w = threadIdx.x >> 5;
    if (lane == 0) sRed[w] = lossLocal;
    __syncthreads();
    if (threadIdx.x == 0){
        float v = 0.f;
        #pragma unroll
        for (int i = 0; i < THREADS / 32; i++) v += sRed[i];
        g_partial[blockIdx.x] = v;
        __threadfence();
        unsigned old = atomicAdd(&g_ticket, 1u);
        sLast = (old == (unsigned)(nblocks - 1));
    }
    __syncthreads();

    // Last block to finish performs finalization (deterministic result)
    if (sLast){
        __threadfence();
        const int n_z = Nvec * EDIM;

        int cnt = 0;
        for (int i = threadIdx.x; i < NCODES; i += THREADS){
            cnt += (g_used[i] != 0);
            g_used[i] = 0;                      // reset for next replay
        }
        float s = 0.f;
        for (int i = threadIdx.x; i < nblocks; i += THREADS) s += g_partial[i];

        #pragma unroll
        for (int o = 16; o > 0; o >>= 1){
            s   += __shfl_down_sync(0xffffffff, s, o);
            cnt += __shfl_down_sync(0xffffffff, cnt, o);
        }
        __shared__ float rs[THREADS / 32];
        __shared__ int   rc[THREADS / 32];
        if (lane == 0){ rs[w] = s; rc[w] = cnt; }
        __syncthreads();
        if (threadIdx.x == 0){
            float total = 0.f; int ctotal = 0;
            #pragma unroll
            for (int i = 0; i < THREADS / 32; i++){ total += rs[i]; ctotal += rc[i]; }
            // loss = beta*mean + mean = 1.25 * sum((z_q - z)^2) / n_z
            out[n_z]     = 1.25f * total / (float)n_z;
            out[n_z + 1] = (float)ctotal;
            __threadfence();
            g_ticket = 0;                       // reset for next graph replay
        }
    }
}

extern "C" void kernel_launch(void* const* d_in, const int* in_sizes, int n_in,
                              void* d_out, int out_size)
{
    const float* z   = (const float*)d_in[0];
    const float* emb = (const float*)d_in[1];
    float* out = (float*)d_out;

    const int n_z  = in_sizes[0];      // 2,097,152
    const int Nvec = n_z / EDIM;       // 262,144

    const int part = Nvec / QPT;
    const int nblocks = (part + THREADS - 1) / THREADS;   // 1024
    vq_main<<<nblocks, THREADS>>>(z, emb, out, Nvec, nblocks);
}